// round 15
// baseline (speedup 1.0000x reference)
#include <cuda_runtime.h>

#define NG   4096
#define HH   128
#define WW   128
#define NPIX (HH*WW)
#define EPSF 1e-6f
#define LOG2E 1.4426950408889634f
#define SXY  31.75f   // (128-1)/2 * 0.5
#define OFFC 63.5f
#define GPB  64       // gaussians per chunk
#define NCHUNK (NG/GPB)
#define NXB  (NPIX/1024)       // 16 pixel row-groups (1024 px each)
#define NBLK (NXB*NCHUNK)      // 1024 render blocks

// Accumulator + sync state. Zero at module load; leaders restore everything
// to zero at the end of every launch -> deterministic across graph replays.
__device__ float g_accum[NPIX];
__device__ unsigned int g_c1[NXB];   // per-group arrivals (64 each)
__device__ unsigned int g_c2;        // leader arrivals (16)
__device__ unsigned int g_c3;        // leader departures (16)
__device__ int g_max;                // global max as int (values >= 0)

typedef unsigned long long u64;

__device__ __forceinline__ u64 pack2(float a, float b) {
    u64 r; asm("mov.b64 %0, {%1, %2};" : "=l"(r) : "f"(a), "f"(b)); return r;
}
__device__ __forceinline__ u64 fma2(u64 a, u64 b, u64 c) {
    u64 d; asm("fma.rn.f32x2 %0, %1, %2, %3;" : "=l"(d) : "l"(a), "l"(b), "l"(c)); return d;
}
__device__ __forceinline__ u64 add2(u64 a, u64 b) {
    u64 d; asm("add.rn.f32x2 %0, %1, %2;" : "=l"(d) : "l"(a), "l"(b)); return d;
}
__device__ __forceinline__ u64 mul2(u64 a, u64 b) {
    u64 d; asm("mul.rn.f32x2 %0, %1, %2;" : "=l"(d) : "l"(a), "l"(b)); return d;
}
__device__ __forceinline__ void unpack2(float& lo, float& hi, u64 v) {
    asm("mov.b64 {%0, %1}, %2;" : "=f"(lo), "=f"(hi) : "l"(v));
}
__device__ __forceinline__ float ex2(float x) {
    float r; asm("ex2.approx.ftz.f32 %0, %1;" : "=f"(r) : "f"(x)); return r;
}
__device__ __forceinline__ u64 ex2_2(u64 v) {
    float lo, hi; unpack2(lo, hi, v);
    return pack2(ex2(lo), ex2(hi));
}

// Polynomial exp2 on a packed f32x2 (both halves), for x <= ~0.5.
// Magic-number rint + degree-4 Taylor of 2^f (|f|<=0.5, rel err <= 4.2e-5),
// exponent scale rebuilt with integer ops on the (idle) ALU pipe.
// Underflow (x < -127) clamps the exponent to zero scale -> result 0.
#define EXP2_MAGIC 12582912.0f          /* 2^23 * 1.5, bits 0x4B400000 */
#define EXP2_BIAS  (127 - 0x4B400000)   /* added to float bits of y     */
__device__ __forceinline__ u64 exp2_poly2(u64 x, u64 kMagic, u64 kNeg1,
                                          u64 kOne, u64 kC1, u64 kC2,
                                          u64 kC3, u64 kC4) {
    u64 y = add2(x, kMagic);            // rint via magic (round-to-even)
    u64 r = fma2(kMagic, kNeg1, y);     // r = y - magic = rint(x)
    u64 f = fma2(r, kNeg1, x);          // f = x - r, |f| <= 0.5
    u64 p = fma2(kC4, f, kC3);          // Taylor: 2^f
    p = fma2(p, f, kC2);
    p = fma2(p, f, kC1);
    p = fma2(p, f, kOne);
    float ylo, yhi; unpack2(ylo, yhi, y);
    int il = (int)(__float_as_uint(ylo) + (unsigned)EXP2_BIAS);
    int ih = (int)(__float_as_uint(yhi) + (unsigned)EXP2_BIAS);
    il = il > 0 ? il : 0;               // x < -127 -> scale 0 (flush)
    ih = ih > 0 ? ih : 0;
    u64 s = pack2(__int_as_float(il << 23), __int_as_float(ih << 23));
    return mul2(p, s);                  // 2^x = 2^f * 2^r
}

// Per-gaussian projection -> expanded quadratic coefficients, written to smem.
// sc layout (pair-interleaved): pair p holds [A0,A1,B0,B1,C0,C1,D0,D1,E0,E1,F0,F1]
__device__ __forceinline__ void prep_one(int n, int li, float* sc,
                                         const float* __restrict__ means,
                                         const float* __restrict__ raw_scales,
                                         const float* __restrict__ rotors,
                                         float t, float angle)
{
    float r[8];
#pragma unroll
    for (int i = 0; i < 8; i++) r[i] = rotors[8*n + i];

    float q1w = r[0], q1x = r[4], q1y = r[5], q1z = r[6];
    {
        float n2 = q1w*q1w + q1x*q1x + q1y*q1y + q1z*q1z;
        float inv = rsqrtf(fmaxf(n2, 1e-24f));
        q1w *= inv; q1x *= inv; q1y *= inv; q1z *= inv;
    }
    float q2w = r[7], q2x = -r[1], q2y = -r[2], q2z = -r[3];
    {
        float n2 = q2w*q2w + q2x*q2x + q2y*q2y + q2z*q2z;
        float inv = rsqrtf(fmaxf(n2, 1e-24f));
        q2w *= inv; q2x *= inv; q2y *= inv; q2z *= inv;
    }

    float L[4][4]  = {{q1w,-q1x,-q1y,-q1z},
                      {q1x, q1w,-q1z, q1y},
                      {q1y, q1z, q1w,-q1x},
                      {q1z,-q1y, q1x, q1w}};
    float Rm[4][4] = {{ q2w, q2x, q2y, q2z},
                      {-q2x, q2w, q2z,-q2y},
                      {-q2y,-q2z, q2w, q2x},
                      {-q2z, q2y,-q2x, q2w}};
    float R4[4][4];
#pragma unroll
    for (int i = 0; i < 4; i++)
#pragma unroll
        for (int k = 0; k < 4; k++)
            R4[i][k] = L[i][0]*Rm[0][k] + L[i][1]*Rm[1][k]
                     + L[i][2]*Rm[2][k] + L[i][3]*Rm[3][k];

    float s2[4];
#pragma unroll
    for (int j = 0; j < 4; j++) s2[j] = __expf(2.f * raw_scales[4*n + j]);

    float cov[4][4];
#pragma unroll
    for (int i = 0; i < 4; i++)
#pragma unroll
        for (int k = i; k < 4; k++)
            cov[i][k] = R4[i][0]*s2[0]*R4[k][0] + R4[i][1]*s2[1]*R4[k][1]
                      + R4[i][2]*s2[2]*R4[k][2] + R4[i][3]*s2[3]*R4[k][3];

    float Wm   = fmaxf(cov[3][3], EPSF);
    float invW = __fdividef(1.f, Wm);
    float td   = t - means[4*n + 3];

    float mx = means[4*n+0] + cov[0][3] * td * invW;
    float my = means[4*n+1] + cov[1][3] * td * invW;
    float mz = means[4*n+2] + cov[2][3] * td * invW;

    float ca = __cosf(angle), sa = __sinf(angle);
    float mvx = ca*mx + sa*mz;
    float mvy = my;

    float M00 = cov[0][0] - cov[0][3]*cov[0][3]*invW;
    float M01 = cov[0][1] - cov[0][3]*cov[1][3]*invW;
    float M02 = cov[0][2] - cov[0][3]*cov[2][3]*invW;
    float M11 = cov[1][1] - cov[1][3]*cov[1][3]*invW;
    float M12 = cov[1][2] - cov[1][3]*cov[2][3]*invW;

    float c00 = ca*ca*M00 + 2.f*ca*sa*M02 + sa*sa*(cov[2][2] - cov[2][3]*cov[2][3]*invW);
    float c01 = ca*M01 + sa*M12;
    float c11 = M11;

    float a = SXY*SXY*c00 + EPSF;
    float b = SXY*SXY*c01;
    float d = SXY*SXY*c11 + EPSF;
    float invdet = __fdividef(1.f, a*d - b*b);

    float mux = SXY*mvx + OFFC;
    float muy = SXY*mvy + OFFC;

    float A  = -0.5f * LOG2E * d * invdet;
    float B  =         LOG2E * b * invdet;
    float C  = -0.5f * LOG2E * a * invdet;
    float lw = -0.5f * td * td * invW * LOG2E;

    float D_ = -2.f*A*mux - B*muy;
    float E_ = -2.f*C*muy - B*mux;
    float F_ = A*mux*mux + B*mux*muy + C*muy*muy + lw;

    float* dst = sc + 12*(li >> 1) + (li & 1);
    dst[0]  = A;
    dst[2]  = B;
    dst[4]  = C;
    dst[6]  = D_;
    dst[8]  = E_;
    dst[10] = F_;
}

// Single fused kernel. block = (xb, chunk). After rendering, each block does
// 4 atomicAdds WITH RETURNS, consumes the returns (forcing performed-at-L2),
// then tickets g_c1[xb]. Ticket-63 = group leader: re-reads its 1024-pixel
// slice, max-reduces, publishes to g_max, waits for all 16 leaders, scales
// its slice into out, zeros state.
__global__ void __launch_bounds__(256) render_kernel(
    const float* __restrict__ means,
    const float* __restrict__ raw_scales,
    const float* __restrict__ rotors,
    const float* __restrict__ t_ptr,
    const float* __restrict__ angle_ptr,
    float* __restrict__ out)
{
    __shared__ float sc[GPB/2 * 12];   // 1.5 KB
    __shared__ unsigned int s_tk;
    __shared__ float smax[8];
    __shared__ float s_inv;

    if (threadIdx.x < GPB) {
        float t     = *t_ptr;
        float angle = *angle_ptr;
        int n = blockIdx.y * GPB + threadIdx.x;
        prep_one(n, threadIdx.x, sc, means, raw_scales, rotors, t, angle);
    }
    __syncthreads();

    int x  = threadIdx.x & (WW - 1);
    int y0 = blockIdx.x * 8 + ((threadIdx.x >> 7) << 2);
    float xf = (float)x;
    float yf = (float)y0;

    u64 X2   = pack2(xf*xf, xf*xf);
    u64 XY   = pack2(xf*yf, xf*yf);
    u64 Y2   = pack2(yf*yf, yf*yf);
    u64 Xp   = pack2(xf, xf);
    u64 Yp   = pack2(yf, yf);
    u64 Y2p1 = pack2(2.f*yf + 1.f, 2.f*yf + 1.f);

    // constants for the polynomial exp2 lane
    const u64 kMagic = pack2(EXP2_MAGIC, EXP2_MAGIC);
    const u64 kNeg1  = pack2(-1.f, -1.f);
    const u64 kOne   = pack2(1.f, 1.f);
    const u64 kC1    = pack2(0.69314718f,  0.69314718f);
    const u64 kC2    = pack2(0.24022651f,  0.24022651f);
    const u64 kC3    = pack2(0.05550411f,  0.05550411f);
    const u64 kC4    = pack2(0.00961813f,  0.00961813f);

    u64 s0 = 0, s1 = 0, s2 = 0, s3 = 0;
    const ulonglong2* cp = (const ulonglong2*)sc;
#pragma unroll 4
    for (int g = 0; g < GPB/2; g++) {
        ulonglong2 u0 = cp[3*g + 0];   // {A, B}
        ulonglong2 u1 = cp[3*g + 1];   // {C, D}
        ulonglong2 u2 = cp[3*g + 2];   // {E, F}

        u64 e0 = u2.y;
        e0 = fma2(u0.x, X2, e0);
        e0 = fma2(u0.y, XY, e0);
        e0 = fma2(u1.x, Y2, e0);
        e0 = fma2(u1.y, Xp, e0);
        e0 = fma2(u2.x, Yp, e0);

        // forward differences along y: d1 = B*x + C*(2y+1) + E, d2 = 2C
        u64 G  = fma2(u0.y, Xp, fma2(u1.x, Y2p1, u2.x));
        u64 C2 = add2(u1.x, u1.x);
        u64 e1 = add2(e0, G);
        u64 H  = add2(G, C2);
        u64 e2 = add2(e1, H);
        u64 H2 = add2(H, C2);
        u64 e3 = add2(e2, H2);

        // lane 0 on the fma/alu pipes (poly), lanes 1-3 on MUFU
        s0 = add2(s0, exp2_poly2(e0, kMagic, kNeg1, kOne, kC1, kC2, kC3, kC4));
        s1 = add2(s1, ex2_2(e1));
        s2 = add2(s2, ex2_2(e2));
        s3 = add2(s3, ex2_2(e3));
    }

    int base = y0 * WW + x;
    float lo, hi;
    unpack2(lo, hi, s0); float r0 = atomicAdd(&g_accum[base       ], lo + hi);
    unpack2(lo, hi, s1); float r1 = atomicAdd(&g_accum[base +   WW], lo + hi);
    unpack2(lo, hi, s2); float r2 = atomicAdd(&g_accum[base + 2*WW], lo + hi);
    unpack2(lo, hi, s3); float r3 = atomicAdd(&g_accum[base + 3*WW], lo + hi);
    // Consume the returns: forces this thread's adds performed-at-L2 before
    // the barrier below (and thus before our group ticket).
    asm volatile("" :: "f"(r0), "f"(r1), "f"(r2), "f"(r3) : "memory");
    __syncthreads();

    if (threadIdx.x == 0) s_tk = atomicAdd(&g_c1[blockIdx.x], 1u);
    __syncthreads();
    if (s_tk != NCHUNK - 1u) return;

    // ---- group leader: all 64 blocks' adds to rows [8*xb, 8*xb+8) done ----
    float f0 = __ldcg(&g_accum[base       ]);
    float f1 = __ldcg(&g_accum[base +   WW]);
    float f2 = __ldcg(&g_accum[base + 2*WW]);
    float f3 = __ldcg(&g_accum[base + 3*WW]);

    float m = fmaxf(fmaxf(f0, f1), fmaxf(f2, f3));
#pragma unroll
    for (int o = 16; o; o >>= 1)
        m = fmaxf(m, __shfl_xor_sync(0xFFFFFFFFu, m, o));
    if ((threadIdx.x & 31) == 0) smax[threadIdx.x >> 5] = m;
    __syncthreads();

    if (threadIdx.x == 0) {
        float bm = smax[0];
#pragma unroll
        for (int i = 1; i < 8; i++) bm = fmaxf(bm, smax[i]);
        atomicMax(&g_max, __float_as_int(bm));   // bm >= 0: int-compare valid
        __threadfence();                          // order max before arrival
        atomicAdd(&g_c2, 1u);
        while (atomicAdd(&g_c2, 0u) < NXB) { }    // wait for all 16 leaders
        __threadfence();
        int mi = atomicMax(&g_max, 0);            // atomic read of final max
        s_inv = __fdividef(1.f, fmaxf(__int_as_float(mi), EPSF));
    }
    __syncthreads();
    float inv = s_inv;

    out[base       ] = f0 * inv;
    out[base +   WW] = f1 * inv;
    out[base + 2*WW] = f2 * inv;
    out[base + 3*WW] = f3 * inv;

    // reset state for next launch: zero own accumulator slice + own counter
    ((float4*)g_accum)[blockIdx.x * 256 + threadIdx.x] =
        make_float4(0.f, 0.f, 0.f, 0.f);
    if (threadIdx.x == 0) {
        g_c1[blockIdx.x] = 0u;
        unsigned int t3 = atomicAdd(&g_c3, 1u);
        if (t3 == NXB - 1u) {   // all leaders done reading g_c2/g_max
            g_c2 = 0u;
            g_max = 0;
            g_c3 = 0u;
        }
    }
}

extern "C" void kernel_launch(void* const* d_in, const int* in_sizes, int n_in,
                              void* d_out, int out_size)
{
    const float* means      = (const float*)d_in[0];
    const float* raw_scales = (const float*)d_in[1];
    const float* rotors     = (const float*)d_in[2];
    const float* t_ptr      = (const float*)d_in[3];
    const float* angle_ptr  = (const float*)d_in[4];
    float* out = (float*)d_out;

    render_kernel<<<dim3(NXB, NCHUNK), 256>>>(means, raw_scales, rotors,
                                              t_ptr, angle_ptr, out);
}

// round 16
// speedup vs baseline: 1.3401x; 1.3401x over previous
#include <cuda_runtime.h>

#define NG   4096
#define HH   128
#define WW   128
#define NPIX (HH*WW)
#define EPSF 1e-6f
#define LOG2E 1.4426950408889634f
#define SXY  31.75f   // (128-1)/2 * 0.5
#define OFFC 63.5f
#define GPB  64       // gaussians per chunk
#define NCHUNK (NG/GPB)
#define NXB  (HH/16)           // 8 row-groups (16 rows = 2048 px each)
#define NBLK (NXB*NCHUNK)      // 512 render blocks

// Accumulator + sync state. Zero at module load; leaders restore everything
// to zero at the end of every launch -> deterministic across graph replays.
__device__ float g_accum[NPIX];
__device__ unsigned int g_c1[NXB];   // per-group arrivals (64 each)
__device__ unsigned int g_c2;        // leader arrivals (8)
__device__ unsigned int g_c3;        // leader departures (8)
__device__ int g_max;                // global max as int (values >= 0)

typedef unsigned long long u64;

__device__ __forceinline__ u64 pack2(float a, float b) {
    u64 r; asm("mov.b64 %0, {%1, %2};" : "=l"(r) : "f"(a), "f"(b)); return r;
}
__device__ __forceinline__ u64 fma2(u64 a, u64 b, u64 c) {
    u64 d; asm("fma.rn.f32x2 %0, %1, %2, %3;" : "=l"(d) : "l"(a), "l"(b), "l"(c)); return d;
}
__device__ __forceinline__ u64 add2(u64 a, u64 b) {
    u64 d; asm("add.rn.f32x2 %0, %1, %2;" : "=l"(d) : "l"(a), "l"(b)); return d;
}
__device__ __forceinline__ u64 mul2(u64 a, u64 b) {
    u64 d; asm("mul.rn.f32x2 %0, %1, %2;" : "=l"(d) : "l"(a), "l"(b)); return d;
}
__device__ __forceinline__ void unpack2(float& lo, float& hi, u64 v) {
    asm("mov.b64 {%0, %1}, %2;" : "=f"(lo), "=f"(hi) : "l"(v));
}
__device__ __forceinline__ float ex2(float x) {
    float r; asm("ex2.approx.ftz.f32 %0, %1;" : "=f"(r) : "f"(x)); return r;
}
__device__ __forceinline__ u64 ex2_2(u64 v) {
    float lo, hi; unpack2(lo, hi, v);
    return pack2(ex2(lo), ex2(hi));
}
// exp2 of both halves with clamp at +126 (avoid inf -> 0*inf NaN downstream)
__device__ __forceinline__ u64 ex2c_2(u64 v) {
    float lo, hi; unpack2(lo, hi, v);
    lo = fminf(lo, 126.f); hi = fminf(hi, 126.f);
    return pack2(ex2(lo), ex2(hi));
}

// Per-gaussian projection -> expanded quadratic coefficients + row factor,
// written to smem. Pair-interleaved, 16-float stride per pair:
// [A0,A1, B0,B1, C0,C1, D0,D1, E0,E1, F0,F1, P0,P1, pad,pad], P = 2^(2C).
__device__ __forceinline__ void prep_one(int n, int li, float* sc,
                                         const float* __restrict__ means,
                                         const float* __restrict__ raw_scales,
                                         const float* __restrict__ rotors,
                                         float t, float angle)
{
    float r[8];
#pragma unroll
    for (int i = 0; i < 8; i++) r[i] = rotors[8*n + i];

    float q1w = r[0], q1x = r[4], q1y = r[5], q1z = r[6];
    {
        float n2 = q1w*q1w + q1x*q1x + q1y*q1y + q1z*q1z;
        float inv = rsqrtf(fmaxf(n2, 1e-24f));
        q1w *= inv; q1x *= inv; q1y *= inv; q1z *= inv;
    }
    float q2w = r[7], q2x = -r[1], q2y = -r[2], q2z = -r[3];
    {
        float n2 = q2w*q2w + q2x*q2x + q2y*q2y + q2z*q2z;
        float inv = rsqrtf(fmaxf(n2, 1e-24f));
        q2w *= inv; q2x *= inv; q2y *= inv; q2z *= inv;
    }

    float L[4][4]  = {{q1w,-q1x,-q1y,-q1z},
                      {q1x, q1w,-q1z, q1y},
                      {q1y, q1z, q1w,-q1x},
                      {q1z,-q1y, q1x, q1w}};
    float Rm[4][4] = {{ q2w, q2x, q2y, q2z},
                      {-q2x, q2w, q2z,-q2y},
                      {-q2y,-q2z, q2w, q2x},
                      {-q2z, q2y,-q2x, q2w}};
    float R4[4][4];
#pragma unroll
    for (int i = 0; i < 4; i++)
#pragma unroll
        for (int k = 0; k < 4; k++)
            R4[i][k] = L[i][0]*Rm[0][k] + L[i][1]*Rm[1][k]
                     + L[i][2]*Rm[2][k] + L[i][3]*Rm[3][k];

    float s2[4];
#pragma unroll
    for (int j = 0; j < 4; j++) s2[j] = __expf(2.f * raw_scales[4*n + j]);

    float cov[4][4];
#pragma unroll
    for (int i = 0; i < 4; i++)
#pragma unroll
        for (int k = i; k < 4; k++)
            cov[i][k] = R4[i][0]*s2[0]*R4[k][0] + R4[i][1]*s2[1]*R4[k][1]
                      + R4[i][2]*s2[2]*R4[k][2] + R4[i][3]*s2[3]*R4[k][3];

    float Wm   = fmaxf(cov[3][3], EPSF);
    float invW = __fdividef(1.f, Wm);
    float td   = t - means[4*n + 3];

    float mx = means[4*n+0] + cov[0][3] * td * invW;
    float my = means[4*n+1] + cov[1][3] * td * invW;
    float mz = means[4*n+2] + cov[2][3] * td * invW;

    float ca = __cosf(angle), sa = __sinf(angle);
    float mvx = ca*mx + sa*mz;
    float mvy = my;

    float M00 = cov[0][0] - cov[0][3]*cov[0][3]*invW;
    float M01 = cov[0][1] - cov[0][3]*cov[1][3]*invW;
    float M02 = cov[0][2] - cov[0][3]*cov[2][3]*invW;
    float M11 = cov[1][1] - cov[1][3]*cov[1][3]*invW;
    float M12 = cov[1][2] - cov[1][3]*cov[2][3]*invW;

    float c00 = ca*ca*M00 + 2.f*ca*sa*M02 + sa*sa*(cov[2][2] - cov[2][3]*cov[2][3]*invW);
    float c01 = ca*M01 + sa*M12;
    float c11 = M11;

    float a = SXY*SXY*c00 + EPSF;
    float b = SXY*SXY*c01;
    float d = SXY*SXY*c11 + EPSF;
    float invdet = __fdividef(1.f, a*d - b*b);

    float mux = SXY*mvx + OFFC;
    float muy = SXY*mvy + OFFC;

    float A  = -0.5f * LOG2E * d * invdet;
    float B  =         LOG2E * b * invdet;
    float C  = -0.5f * LOG2E * a * invdet;
    float lw = -0.5f * td * td * invW * LOG2E;

    float D_ = -2.f*A*mux - B*muy;
    float E_ = -2.f*C*muy - B*mux;
    float F_ = A*mux*mux + B*mux*muy + C*muy*muy + lw;

    float* dst = sc + 16*(li >> 1) + (li & 1);
    dst[0]  = A;
    dst[2]  = B;
    dst[4]  = C;
    dst[6]  = D_;
    dst[8]  = E_;
    dst[10] = F_;
    dst[12] = ex2(2.f * C);   // P: per-row multiplier update factor (<= 1)
}

// Single fused kernel. block = (xb, chunk). Threads 0..GPB-1 prep the chunk
// into smem; all 256 threads render a 16-row band (8 rows per thread) using
// MULTIPLICATIVE forward differencing: per gaussian-column only 3 exps
// (anchors at y0 and y0+4, plus the row-ratio 2^G); rows rebuilt with mul2.
// REDG into g_accum; R14-style leader epilogue.
__global__ void __launch_bounds__(256) render_kernel(
    const float* __restrict__ means,
    const float* __restrict__ raw_scales,
    const float* __restrict__ rotors,
    const float* __restrict__ t_ptr,
    const float* __restrict__ angle_ptr,
    float* __restrict__ out)
{
    __shared__ float sc[GPB/2 * 16];   // 2 KB
    __shared__ unsigned int s_tk;
    __shared__ float smax[8];
    __shared__ float s_inv;

    if (threadIdx.x < GPB) {
        float t     = *t_ptr;
        float angle = *angle_ptr;
        int n = blockIdx.y * GPB + threadIdx.x;
        prep_one(n, threadIdx.x, sc, means, raw_scales, rotors, t, angle);
    }
    __syncthreads();

    int x  = threadIdx.x & (WW - 1);
    int y0 = blockIdx.x * 16 + ((threadIdx.x >> 7) << 3);
    float xf = (float)x;
    float yf = (float)y0;

    u64 X2   = pack2(xf*xf, xf*xf);
    u64 XY   = pack2(xf*yf, xf*yf);
    u64 Y2   = pack2(yf*yf, yf*yf);
    u64 Xp   = pack2(xf, xf);
    u64 Yp   = pack2(yf, yf);
    u64 Y2p1 = pack2(2.f*yf + 1.f, 2.f*yf + 1.f);
    const u64 k4  = pack2(4.f, 4.f);
    const u64 k12 = pack2(12.f, 12.f);

    u64 s0 = 0, s1 = 0, s2 = 0, s3 = 0, s4 = 0, s5 = 0, s6 = 0, s7 = 0;
    const ulonglong2* cp = (const ulonglong2*)sc;
#pragma unroll 4
    for (int g = 0; g < GPB/2; g++) {
        ulonglong2 u0 = cp[4*g + 0];   // {A, B}
        ulonglong2 u1 = cp[4*g + 1];   // {C, D}
        ulonglong2 u2 = cp[4*g + 2];   // {E, F}
        ulonglong2 u3 = cp[4*g + 3];   // {P, pad}

        // e0 at (x, y0)
        u64 e0 = u2.y;
        e0 = fma2(u0.x, X2, e0);
        e0 = fma2(u0.y, XY, e0);
        e0 = fma2(u1.x, Y2, e0);
        e0 = fma2(u1.y, Xp, e0);
        e0 = fma2(u2.x, Yp, e0);

        // G = e(y0+1)-e(y0) = B*x + C*(2y0+1) + E ;  e4 = e0 + 4G + 12C
        u64 G  = fma2(u0.y, Xp, fma2(u1.x, Y2p1, u2.x));
        u64 e4 = fma2(k12, u1.x, fma2(k4, G, e0));

        u64 vA = ex2_2(e0);        // anchor rows y0 and y0+4
        u64 vB = ex2_2(e4);
        u64 gm = ex2c_2(G);        // row ratio (clamped to finite)
        u64 P  = u3.x;             // ratio update factor 2^(2C)

        s0 = add2(s0, vA);
        vA = mul2(vA, gm);                   s1 = add2(s1, vA);  // r1: *2^G
        gm = mul2(gm, P); vA = mul2(vA, gm); s2 = add2(s2, vA);  // r2: *2^(G+2C)
        gm = mul2(gm, P); vA = mul2(vA, gm); s3 = add2(s3, vA);  // r3: *2^(G+4C)
        gm = mul2(gm, P); gm = mul2(gm, P);                      // skip to 2^(G+8C)
        s4 = add2(s4, vB);
        vB = mul2(vB, gm);                   s5 = add2(s5, vB);  // r5
        gm = mul2(gm, P); vB = mul2(vB, gm); s6 = add2(s6, vB);  // r6
        gm = mul2(gm, P); vB = mul2(vB, gm); s7 = add2(s7, vB);  // r7
    }

    int base = y0 * WW + x;
    float lo, hi;
    unpack2(lo, hi, s0); float r0 = atomicAdd(&g_accum[base       ], lo + hi);
    unpack2(lo, hi, s1); float r1 = atomicAdd(&g_accum[base +   WW], lo + hi);
    unpack2(lo, hi, s2); float r2 = atomicAdd(&g_accum[base + 2*WW], lo + hi);
    unpack2(lo, hi, s3); float r3 = atomicAdd(&g_accum[base + 3*WW], lo + hi);
    unpack2(lo, hi, s4); float r4 = atomicAdd(&g_accum[base + 4*WW], lo + hi);
    unpack2(lo, hi, s5); float r5 = atomicAdd(&g_accum[base + 5*WW], lo + hi);
    unpack2(lo, hi, s6); float r6 = atomicAdd(&g_accum[base + 6*WW], lo + hi);
    unpack2(lo, hi, s7); float r7 = atomicAdd(&g_accum[base + 7*WW], lo + hi);
    // Consume the returns: forces this thread's adds performed-at-L2 before
    // the group ticket below.
    asm volatile("" :: "f"(r0), "f"(r1), "f"(r2), "f"(r3),
                       "f"(r4), "f"(r5), "f"(r6), "f"(r7) : "memory");
    __syncthreads();

    if (threadIdx.x == 0) s_tk = atomicAdd(&g_c1[blockIdx.x], 1u);
    __syncthreads();
    if (s_tk != NCHUNK - 1u) return;

    // ---- group leader: all 64 blocks' adds to rows [16*xb,16*xb+16) done ----
    float f[8];
#pragma unroll
    for (int i = 0; i < 8; i++) f[i] = __ldcg(&g_accum[base + i*WW]);

    float m = 0.f;
#pragma unroll
    for (int i = 0; i < 8; i++) m = fmaxf(m, f[i]);
#pragma unroll
    for (int o = 16; o; o >>= 1)
        m = fmaxf(m, __shfl_xor_sync(0xFFFFFFFFu, m, o));
    if ((threadIdx.x & 31) == 0) smax[threadIdx.x >> 5] = m;
    __syncthreads();

    if (threadIdx.x == 0) {
        float bm = smax[0];
#pragma unroll
        for (int i = 1; i < 8; i++) bm = fmaxf(bm, smax[i]);
        atomicMax(&g_max, __float_as_int(bm));   // bm >= 0: int-compare valid
        __threadfence();                          // order max before arrival
        atomicAdd(&g_c2, 1u);
        while (atomicAdd(&g_c2, 0u) < NXB) { }    // wait for all 8 leaders
        __threadfence();
        int mi = atomicMax(&g_max, 0);            // atomic read of final max
        s_inv = __fdividef(1.f, fmaxf(__int_as_float(mi), EPSF));
    }
    __syncthreads();
    float inv = s_inv;

#pragma unroll
    for (int i = 0; i < 8; i++) out[base + i*WW] = f[i] * inv;

    // reset state for next launch: zero own accumulator slice + own counter
    ((float4*)g_accum)[blockIdx.x * 512 + threadIdx.x      ] = make_float4(0.f, 0.f, 0.f, 0.f);
    ((float4*)g_accum)[blockIdx.x * 512 + threadIdx.x + 256] = make_float4(0.f, 0.f, 0.f, 0.f);
    if (threadIdx.x == 0) {
        g_c1[blockIdx.x] = 0u;
        unsigned int t3 = atomicAdd(&g_c3, 1u);
        if (t3 == NXB - 1u) {   // all leaders done reading g_c2/g_max
            g_c2 = 0u;
            g_max = 0;
            g_c3 = 0u;
        }
    }
}

extern "C" void kernel_launch(void* const* d_in, const int* in_sizes, int n_in,
                              void* d_out, int out_size)
{
    const float* means      = (const float*)d_in[0];
    const float* raw_scales = (const float*)d_in[1];
    const float* rotors     = (const float*)d_in[2];
    const float* t_ptr      = (const float*)d_in[3];
    const float* angle_ptr  = (const float*)d_in[4];
    float* out = (float*)d_out;

    render_kernel<<<dim3(NXB, NCHUNK), 256>>>(means, raw_scales, rotors,
                                              t_ptr, angle_ptr, out);
}